// round 16
// baseline (speedup 1.0000x reference)
#include <cuda_runtime.h>
#include <cuda_fp16.h>
#include <stdint.h>
#include <math.h>

#define N_NODES 50000
#define N_EDGES 800000
#define EP      (N_EDGES + N_NODES)   // edges incl. self-loops = 850000
#define DIM     256
#define NH      8
#define NBLK    ((N_NODES + 255) / 256)   // 196 scan blocks

// ---------------- static device scratch (no allocs allowed) ----------------
__device__ __align__(16) unsigned g_xlh[(size_t)N_NODES * DIM / 2]; // x@Wl, half2
__device__ __align__(16) unsigned g_xrh[(size_t)N_NODES * DIM / 2]; // x@Wr, half2
__device__ __align__(16) unsigned g_hh [(size_t)N_NODES * DIM / 2]; // layer-1 out, half2
__device__ __align__(16) unsigned g_wt [4 * DIM * DIM / 2];        // W^T fp16 [mat][n][k]
__device__ int g_deg [N_NODES];        // statically zero; re-zeroed in scan3 each call
__device__ int g_roff[N_NODES + 1];
__device__ int g_cur [N_NODES];
__device__ int g_csr [EP];
__device__ int g_part[256];
__device__ int g_is64;

__device__ __forceinline__ unsigned h2u(float a, float b) {
    __half2 h = __floats2half2_rn(a, b);
    return *(unsigned*)&h;
}

__device__ __forceinline__ int load_idx(const void* e, size_t i) {
    return g_is64 ? (int)((const long long*)e)[i] : ((const int*)e)[i];
}

// ---------------- edge dtype detection ----------------
__global__ void detect_kernel(const int* __restrict__ e) {
    int zeros = 0;
#pragma unroll
    for (int j = 1; j < 128; j += 2) zeros += (e[j] == 0);
    g_is64 = (zeros >= 32);
}

// ---------------- W transpose + fp16 convert (once per call) ---------------
__global__ void convwt_kernel(const float* __restrict__ Wl1, const float* __restrict__ Wr1,
                              const float* __restrict__ Wl2, const float* __restrict__ Wr2) {
    int i = blockIdx.x * 256 + threadIdx.x;   // 32768 words per matrix
    int m = blockIdx.y;
    const float* W = (m == 0) ? Wl1 : (m == 1) ? Wr1 : (m == 2) ? Wl2 : Wr2;
    int n  = i >> 7;
    int kw = i & 127;
    int k  = kw * 2;
    g_wt[m * (DIM * DIM / 2) + i] = h2u(W[(size_t)k * DIM + n], W[(size_t)(k + 1) * DIM + n]);
}

// ---------------- CSR build (deg counts real edges only; self-loops implicit)
__global__ void hist_kernel(const void* __restrict__ eidx) {
    int e = blockIdx.x * blockDim.x + threadIdx.x;
    if (e < N_EDGES) atomicAdd(&g_deg[load_idx(eidx, (size_t)N_EDGES + e)], 1);
}

__global__ void scan1_kernel() {
    __shared__ int sh[256];
    int t = threadIdx.x;
    int i = blockIdx.x * 256 + t;
    int v = (i < N_NODES) ? g_deg[i] : 0;
    sh[t] = v;
    __syncthreads();
#pragma unroll
    for (int off = 1; off < 256; off <<= 1) {
        int u = (t >= off) ? sh[t - off] : 0;
        __syncthreads();
        sh[t] += u;
        __syncthreads();
    }
    if (i < N_NODES) g_roff[i] = sh[t] - v;
    if (t == 255) g_part[blockIdx.x] = sh[255];
}

__global__ void scan3_kernel() {
    __shared__ int sh[256];
    int t = threadIdx.x;
    sh[t] = (t < NBLK) ? g_part[t] : 0;
    __syncthreads();
#pragma unroll
    for (int off = 1; off < 256; off <<= 1) {
        int u = (t >= off) ? sh[t - off] : 0;
        __syncthreads();
        sh[t] += u;
        __syncthreads();
    }
    int pofs = (blockIdx.x > 0) ? sh[blockIdx.x - 1] : 0;
    int i = blockIdx.x * 256 + t;
    if (i < N_NODES) {
        int val = g_roff[i] + pofs + i;
        g_roff[i]  = val;
        g_csr[val] = i;                   // self-loop first
        g_cur[i]   = val + 1;
        g_deg[i]   = 0;                   // reset for next replay
    }
    if (i == 0) g_roff[N_NODES] = EP;
}

__global__ void scatter_kernel(const void* __restrict__ eidx) {
    int e = blockIdx.x * blockDim.x + threadIdx.x;
    if (e >= N_EDGES) return;
    int src = load_idx(eidx, e);
    int dst = load_idx(eidx, (size_t)N_EDGES + e);
    int pos = atomicAdd(&g_cur[dst], 1);
    g_csr[pos] = src;
}

// ---------------- fp16 tensor-core GEMM with ldmatrix fragment loads -------
#define TBM 128
#define TBN 128
#define TBK 32
#define ST  20
#define TILE_SZ (128 * ST)

__device__ __forceinline__ void mma_f16(float* d,
                                        unsigned a0, unsigned a1,
                                        unsigned a2, unsigned a3,
                                        unsigned b0, unsigned b1) {
    asm volatile(
        "mma.sync.aligned.m16n8k16.row.col.f32.f16.f16.f32 "
        "{%0,%1,%2,%3}, {%4,%5,%6,%7}, {%8,%9}, {%0,%1,%2,%3};"
        : "+f"(d[0]), "+f"(d[1]), "+f"(d[2]), "+f"(d[3])
        : "r"(a0), "r"(a1), "r"(a2), "r"(a3), "r"(b0), "r"(b1));
}

__device__ __forceinline__ void ldsm_x4(unsigned& a0, unsigned& a1,
                                        unsigned& a2, unsigned& a3, uint32_t addr) {
    asm volatile("ldmatrix.sync.aligned.m8n8.x4.shared.b16 {%0,%1,%2,%3}, [%4];"
                 : "=r"(a0), "=r"(a1), "=r"(a2), "=r"(a3) : "r"(addr));
}
__device__ __forceinline__ void ldsm_x2(unsigned& b0, unsigned& b1, uint32_t addr) {
    asm volatile("ldmatrix.sync.aligned.m8n8.x2.shared.b16 {%0,%1}, [%2];"
                 : "=r"(b0), "=r"(b1) : "r"(addr));
}

__global__ __launch_bounds__(256, 2)
void gemm_f16_kernel(const float* __restrict__ Xin, int layer) {
    __shared__ __align__(16) unsigned As2[2][TILE_SZ];
    __shared__ __align__(16) unsigned Bs2[2][TILE_SZ];

    int m0 = blockIdx.x * TBM;
    int n0 = blockIdx.y * TBN;
    int mat = layer * 2 + blockIdx.z;
    const unsigned* WT = g_wt + (size_t)mat * (DIM * DIM / 2);

    int tid = threadIdx.x;
    int wid = tid >> 5, lane = tid & 31;
    int warp_m = wid & 1;
    int warp_n = wid >> 1;
    int g4 = lane >> 2;
    int t4 = lane & 3;

    int xrow[4], xk4[4];
    int hrow[2], hc[2];
#pragma unroll
    for (int t = 0; t < 4; t++) {
        int f = tid + t * 256;
        xrow[t] = f >> 3;  xk4[t] = (f & 7) << 2;
    }
#pragma unroll
    for (int t = 0; t < 2; t++) {
        int f = tid + t * 256;
        hrow[t] = f >> 2;  hc[t] = (f & 3) << 2;
    }

    float4 xv[4];
    uint4  hv[2];
    uint4  wv[2];

    auto load_tile = [&](int k0) {
        int kw = k0 >> 1;
        if (layer == 0) {
#pragma unroll
            for (int t = 0; t < 4; t++) {
                int gr = m0 + xrow[t];
                xv[t] = make_float4(0.f, 0.f, 0.f, 0.f);
                if (gr < N_NODES)
                    xv[t] = *(const float4*)(Xin + (size_t)gr * DIM + k0 + xk4[t]);
            }
        } else {
#pragma unroll
            for (int t = 0; t < 2; t++) {
                int gr = m0 + hrow[t];
                hv[t] = make_uint4(0u, 0u, 0u, 0u);
                if (gr < N_NODES)
                    hv[t] = *(const uint4*)(g_hh + (size_t)gr * (DIM / 2) + kw + hc[t]);
            }
        }
#pragma unroll
        for (int t = 0; t < 2; t++)
            wv[t] = *(const uint4*)(WT + (size_t)(n0 + hrow[t]) * (DIM / 2) + kw + hc[t]);
    };

    auto store_tile = [&](int p) {
        unsigned* As = As2[p];
        unsigned* Bs = Bs2[p];
        if (layer == 0) {
#pragma unroll
            for (int t = 0; t < 4; t++) {
                uint2 u;
                u.x = h2u(xv[t].x, xv[t].y);
                u.y = h2u(xv[t].z, xv[t].w);
                *(uint2*)&As[xrow[t] * ST + (xk4[t] >> 1)] = u;
            }
        } else {
#pragma unroll
            for (int t = 0; t < 2; t++)
                *(uint4*)&As[hrow[t] * ST + hc[t]] = hv[t];
        }
#pragma unroll
        for (int t = 0; t < 2; t++)
            *(uint4*)&Bs[hrow[t] * ST + hc[t]] = wv[t];
    };

    float acc[4][4][4];
#pragma unroll
    for (int mt = 0; mt < 4; mt++)
#pragma unroll
        for (int nt = 0; nt < 4; nt++)
#pragma unroll
            for (int r = 0; r < 4; r++) acc[mt][nt][r] = 0.f;

    load_tile(0);
    store_tile(0);
    __syncthreads();
    load_tile(TBK);

    uint32_t a_lane_off = (uint32_t)(((warp_m * 64 + (lane & 15)) * ST + (lane >> 4) * 4) * 4);
    uint32_t b_lane_off = (uint32_t)(((warp_n * 32 + (lane & 7)) * ST + ((lane >> 3) & 1) * 4) * 4);

    int p = 0;
    for (int k0 = 0; k0 < DIM; k0 += TBK) {
        uint32_t sa  = (uint32_t)__cvta_generic_to_shared(As2[p]) + a_lane_off;
        uint32_t sbb = (uint32_t)__cvta_generic_to_shared(Bs2[p]) + b_lane_off;

#pragma unroll
        for (int ks = 0; ks < 2; ks++) {
            unsigned b[4][2];
#pragma unroll
            for (int nt = 0; nt < 4; nt++)
                ldsm_x2(b[nt][0], b[nt][1], sbb + (uint32_t)((nt * 8 * ST + ks * 8) * 4));
#pragma unroll
            for (int mt = 0; mt < 4; mt++) {
                unsigned a0, a1, a2, a3;
                ldsm_x4(a0, a1, a2, a3, sa + (uint32_t)((mt * 16 * ST + ks * 8) * 4));
#pragma unroll
                for (int nt = 0; nt < 4; nt++)
                    mma_f16(acc[mt][nt], a0, a1, a2, a3, b[nt][0], b[nt][1]);
            }
        }

        if (k0 + TBK < DIM) {
            store_tile(1 - p);
            if (k0 + 2 * TBK < DIM) load_tile(k0 + 2 * TBK);
            __syncthreads();
        }
        p ^= 1;
    }

    unsigned* Cout = (blockIdx.z == 0) ? g_xlh : g_xrh;
#pragma unroll
    for (int mt = 0; mt < 4; mt++) {
        int r0 = m0 + warp_m * 64 + mt * 16 + g4;
#pragma unroll
        for (int nt = 0; nt < 4; nt++) {
            int c = n0 + warp_n * 32 + nt * 8 + t4 * 2;
            if (r0 < N_NODES)
                Cout[((size_t)r0 * DIM + c) >> 1] =
                    h2u(acc[mt][nt][0], acc[mt][nt][1]);
            if (r0 + 8 < N_NODES)
                Cout[((size_t)(r0 + 8) * DIM + c) >> 1] =
                    h2u(acc[mt][nt][2], acc[mt][nt][3]);
        }
    }
}

// ---------------- fused GATv2 node kernel (warp/node, 4-edge batches) ------
__device__ __forceinline__ float dot4_lrelu(float4 a, float4 l, float4 r) {
    float z, s;
    z = l.x + r.x; z = z > 0.f ? z : 0.2f * z; s  = a.x * z;
    z = l.y + r.y; z = z > 0.f ? z : 0.2f * z; s += a.y * z;
    z = l.z + r.z; z = z > 0.f ? z : 0.2f * z; s += a.z * z;
    z = l.w + r.w; z = z > 0.f ? z : 0.2f * z; s += a.w * z;
    return s;
}

__device__ __forceinline__ float4 u2f4(uint2 u) {
    float2 lo = __half22float2(*(__half2*)&u.x);
    float2 hi = __half22float2(*(__half2*)&u.y);
    return make_float4(lo.x, lo.y, hi.x, hi.y);
}

#define WPB 8   // warps per block

__global__ __launch_bounds__(WPB * 32)
void gat_node_kernel(const float* __restrict__ att,
                     const float* __restrict__ bias,
                     float* __restrict__ outp, int mode) {
    int node = blockIdx.x * WPB + (threadIdx.x >> 5);
    if (node >= N_NODES) return;
    int lane = threadIdx.x & 31;
    int grp  = lane >> 3;
    int sub  = lane & 7;

    const float4* pa = (const float4*)att;
    float4 a0 = pa[lane], a1 = pa[lane + 32];
    const uint2* prh = (const uint2*)(g_xrh + (size_t)node * (DIM / 2));
    float4 r0 = u2f4(prh[lane]), r1 = u2f4(prh[lane + 32]);

    int beg = g_roff[node], end = g_roff[node + 1];

    float4 acc0 = make_float4(0.f, 0.f, 0.f, 0.f);
    float4 acc1 = make_float4(0.f, 0.f, 0.f, 0.f);
    float  s0 = 0.f, s1 = 0.f;

    // 4-edge batches, double-buffered. Padded slots duplicate edge `beg`
    // (valid row -> finite scores) and are masked out of accumulation.
    uint2 cur[4][2], nxt[4][2];

    auto load4 = [&](int e, uint2 dst[4][2]) {
#pragma unroll
        for (int j = 0; j < 4; j++) {
            int idx = g_csr[(e + j < end) ? (e + j) : beg];
            const uint2* p = (const uint2*)(g_xlh + (size_t)idx * (DIM / 2));
            dst[j][0] = p[lane];
            dst[j][1] = p[lane + 32];
        }
    };

    load4(beg, cur);

    for (int e = beg; e < end; e += 4) {
        if (e + 4 < end) load4(e + 4, nxt);
        int cnt = end - e;   // uniform per warp

        float sl[4], sh[4];
#pragma unroll
        for (int j = 0; j < 4; j++) {
            float4 l0 = u2f4(cur[j][0]), l1 = u2f4(cur[j][1]);
            sl[j] = dot4_lrelu(a0, l0, r0);
            sh[j] = dot4_lrelu(a1, l1, r1);
        }
        // interleaved shuffle reductions: 8 independent chains
#pragma unroll
        for (int off = 4; off; off >>= 1) {
#pragma unroll
            for (int j = 0; j < 4; j++) {
                sl[j] += __shfl_xor_sync(0xffffffffu, sl[j], off);
                sh[j] += __shfl_xor_sync(0xffffffffu, sh[j], off);
            }
        }
#pragma unroll
        for (int j = 0; j < 4; j++) {
            float ex = 0.f;
            if (sub < 2) ex = __expf(sub == 0 ? sl[j] : sh[j]);
            float exl = __shfl_sync(0xffffffffu, ex, grp * 8);
            float exh = __shfl_sync(0xffffffffu, ex, grp * 8 + 1);
            if (j < cnt) {
                float4 l0 = u2f4(cur[j][0]), l1 = u2f4(cur[j][1]);
                acc0.x += exl * l0.x; acc0.y += exl * l0.y;
                acc0.z += exl * l0.z; acc0.w += exl * l0.w;
                acc1.x += exh * l1.x; acc1.y += exh * l1.y;
                acc1.z += exh * l1.z; acc1.w += exh * l1.w;
                s0 += exl; s1 += exh;
            }
        }

#pragma unroll
        for (int j = 0; j < 4; j++) {
            cur[j][0] = nxt[j][0];
            cur[j][1] = nxt[j][1];
        }
    }

    float inv0 = 1.f / s0, inv1 = 1.f / s1;
    const float4* pb = (const float4*)bias;
    float4 b0 = pb[lane], b1 = pb[lane + 32];

    float4 v0 = make_float4(acc0.x * inv0 + b0.x, acc0.y * inv0 + b0.y,
                            acc0.z * inv0 + b0.z, acc0.w * inv0 + b0.w);
    float4 v1 = make_float4(acc1.x * inv1 + b1.x, acc1.y * inv1 + b1.y,
                            acc1.z * inv1 + b1.z, acc1.w * inv1 + b1.w);

    if (mode == 0) {   // ELU -> half2-packed layer-2 input
        v0.x = v0.x > 0.f ? v0.x : expm1f(v0.x);
        v0.y = v0.y > 0.f ? v0.y : expm1f(v0.y);
        v0.z = v0.z > 0.f ? v0.z : expm1f(v0.z);
        v0.w = v0.w > 0.f ? v0.w : expm1f(v0.w);
        v1.x = v1.x > 0.f ? v1.x : expm1f(v1.x);
        v1.y = v1.y > 0.f ? v1.y : expm1f(v1.y);
        v1.z = v1.z > 0.f ? v1.z : expm1f(v1.z);
        v1.w = v1.w > 0.f ? v1.w : expm1f(v1.w);
        uint2* ph = (uint2*)(g_hh + (size_t)node * (DIM / 2));
        ph[lane]      = make_uint2(h2u(v0.x, v0.y), h2u(v0.z, v0.w));
        ph[lane + 32] = make_uint2(h2u(v1.x, v1.y), h2u(v1.z, v1.w));
    } else {
        float4* po = (float4*)(outp + (size_t)node * DIM);
        po[lane]      = v0;
        po[lane + 32] = v1;
    }
}

// ---------------- host entry ----------------
extern "C" void kernel_launch(void* const* d_in, const int* in_sizes, int n_in,
                              void* d_out, int out_size) {
    const float* x    = (const float*)d_in[0];
    const void*  eidx = d_in[1];
    const float* Wl1  = (const float*)d_in[2];
    const float* Wr1  = (const float*)d_in[3];
    const float* att1 = (const float*)d_in[4];
    const float* b1   = (const float*)d_in[5];
    const float* Wl2  = (const float*)d_in[6];
    const float* Wr2  = (const float*)d_in[7];
    const float* att2 = (const float*)d_in[8];
    const float* b2   = (const float*)d_in[9];
    float*       outp = (float*)d_out;

    dim3 ggemm((N_NODES + TBM - 1) / TBM, DIM / TBN, 2);
    dim3 gnode((N_NODES + WPB - 1) / WPB);

    // ---- one-time prep: W transpose + CSR build ----
    detect_kernel  <<<1, 1>>>((const int*)eidx);
    convwt_kernel  <<<dim3(128, 4), 256>>>(Wl1, Wr1, Wl2, Wr2);
    hist_kernel    <<<(N_EDGES + 255) / 256, 256>>>(eidx);
    scan1_kernel   <<<NBLK, 256>>>();
    scan3_kernel   <<<NBLK, 256>>>();
    scatter_kernel <<<(N_EDGES + 255) / 256, 256>>>(eidx);

    // ---- layer 1 ----
    gemm_f16_kernel<<<ggemm, 256>>>(x, 0);
    gat_node_kernel<<<gnode, WPB * 32>>>(att1, b1, outp, 0);

    // ---- layer 2 ----
    gemm_f16_kernel<<<ggemm, 256>>>(x, 1);
    gat_node_kernel<<<gnode, WPB * 32>>>(att2, b2, outp, 1);
}

// round 17
// speedup vs baseline: 1.1684x; 1.1684x over previous
#include <cuda_runtime.h>
#include <cuda_fp16.h>
#include <stdint.h>
#include <math.h>

#define N_NODES 50000
#define N_EDGES 800000
#define EP      (N_EDGES + N_NODES)   // edges incl. self-loops = 850000
#define DIM     256
#define NH      8
#define NBLK    ((N_NODES + 255) / 256)   // 196 scan blocks

// ---------------- static device scratch (no allocs allowed) ----------------
__device__ __align__(16) unsigned g_xlh[(size_t)N_NODES * DIM / 2]; // x@Wl, half2
__device__ __align__(16) unsigned g_xrh[(size_t)N_NODES * DIM / 2]; // x@Wr, half2
__device__ __align__(16) unsigned g_hh [(size_t)N_NODES * DIM / 2]; // layer-1 out, half2
__device__ __align__(16) unsigned g_wt [4 * DIM * DIM / 2];        // W^T fp16 [mat][n][k]
__device__ int g_deg [N_NODES];        // statically zero; re-zeroed in scan3 each call
__device__ int g_roff[N_NODES + 1];
__device__ int g_cur [N_NODES];
__device__ int g_csr [EP];
__device__ int g_part[256];
__device__ int g_is64;

__device__ __forceinline__ unsigned h2u(float a, float b) {
    __half2 h = __floats2half2_rn(a, b);
    return *(unsigned*)&h;
}

__device__ __forceinline__ int load_idx(const void* e, size_t i) {
    return g_is64 ? (int)((const long long*)e)[i] : ((const int*)e)[i];
}

// ---------------- edge dtype detection ----------------
__global__ void detect_kernel(const int* __restrict__ e) {
    int zeros = 0;
#pragma unroll
    for (int j = 1; j < 128; j += 2) zeros += (e[j] == 0);
    g_is64 = (zeros >= 32);
}

// ---------------- W transpose + fp16 convert (once per call) ---------------
__global__ void convwt_kernel(const float* __restrict__ Wl1, const float* __restrict__ Wr1,
                              const float* __restrict__ Wl2, const float* __restrict__ Wr2) {
    int i = blockIdx.x * 256 + threadIdx.x;   // 32768 words per matrix
    int m = blockIdx.y;
    const float* W = (m == 0) ? Wl1 : (m == 1) ? Wr1 : (m == 2) ? Wl2 : Wr2;
    int n  = i >> 7;
    int kw = i & 127;
    int k  = kw * 2;
    g_wt[m * (DIM * DIM / 2) + i] = h2u(W[(size_t)k * DIM + n], W[(size_t)(k + 1) * DIM + n]);
}

// ---------------- CSR build (deg counts real edges only; self-loops implicit)
__global__ void hist_kernel(const void* __restrict__ eidx) {
    int e = blockIdx.x * blockDim.x + threadIdx.x;
    if (e < N_EDGES) atomicAdd(&g_deg[load_idx(eidx, (size_t)N_EDGES + e)], 1);
}

__global__ void scan1_kernel() {
    __shared__ int sh[256];
    int t = threadIdx.x;
    int i = blockIdx.x * 256 + t;
    int v = (i < N_NODES) ? g_deg[i] : 0;
    sh[t] = v;
    __syncthreads();
#pragma unroll
    for (int off = 1; off < 256; off <<= 1) {
        int u = (t >= off) ? sh[t - off] : 0;
        __syncthreads();
        sh[t] += u;
        __syncthreads();
    }
    if (i < N_NODES) g_roff[i] = sh[t] - v;
    if (t == 255) g_part[blockIdx.x] = sh[255];
}

__global__ void scan3_kernel() {
    __shared__ int sh[256];
    int t = threadIdx.x;
    sh[t] = (t < NBLK) ? g_part[t] : 0;
    __syncthreads();
#pragma unroll
    for (int off = 1; off < 256; off <<= 1) {
        int u = (t >= off) ? sh[t - off] : 0;
        __syncthreads();
        sh[t] += u;
        __syncthreads();
    }
    int pofs = (blockIdx.x > 0) ? sh[blockIdx.x - 1] : 0;
    int i = blockIdx.x * 256 + t;
    if (i < N_NODES) {
        int val = g_roff[i] + pofs + i;
        g_roff[i]  = val;
        g_csr[val] = i;                   // self-loop first
        g_cur[i]   = val + 1;
        g_deg[i]   = 0;                   // reset for next replay
    }
    if (i == 0) g_roff[N_NODES] = EP;
}

__global__ void scatter_kernel(const void* __restrict__ eidx) {
    int e = blockIdx.x * blockDim.x + threadIdx.x;
    if (e >= N_EDGES) return;
    int src = load_idx(eidx, e);
    int dst = load_idx(eidx, (size_t)N_EDGES + e);
    int pos = atomicAdd(&g_cur[dst], 1);
    g_csr[pos] = src;
}

// ---------------- fp16 tensor-core GEMM with ldmatrix fragment loads -------
#define TBM 128
#define TBN 128
#define TBK 32
#define ST  20
#define TILE_SZ (128 * ST)

__device__ __forceinline__ void mma_f16(float* d,
                                        unsigned a0, unsigned a1,
                                        unsigned a2, unsigned a3,
                                        unsigned b0, unsigned b1) {
    asm volatile(
        "mma.sync.aligned.m16n8k16.row.col.f32.f16.f16.f32 "
        "{%0,%1,%2,%3}, {%4,%5,%6,%7}, {%8,%9}, {%0,%1,%2,%3};"
        : "+f"(d[0]), "+f"(d[1]), "+f"(d[2]), "+f"(d[3])
        : "r"(a0), "r"(a1), "r"(a2), "r"(a3), "r"(b0), "r"(b1));
}

__device__ __forceinline__ void ldsm_x4(unsigned& a0, unsigned& a1,
                                        unsigned& a2, unsigned& a3, uint32_t addr) {
    asm volatile("ldmatrix.sync.aligned.m8n8.x4.shared.b16 {%0,%1,%2,%3}, [%4];"
                 : "=r"(a0), "=r"(a1), "=r"(a2), "=r"(a3) : "r"(addr));
}
__device__ __forceinline__ void ldsm_x2(unsigned& b0, unsigned& b1, uint32_t addr) {
    asm volatile("ldmatrix.sync.aligned.m8n8.x2.shared.b16 {%0,%1}, [%2];"
                 : "=r"(b0), "=r"(b1) : "r"(addr));
}

__global__ __launch_bounds__(256, 2)
void gemm_f16_kernel(const float* __restrict__ Xin, int layer) {
    __shared__ __align__(16) unsigned As2[2][TILE_SZ];
    __shared__ __align__(16) unsigned Bs2[2][TILE_SZ];

    int m0 = blockIdx.x * TBM;
    int n0 = blockIdx.y * TBN;
    int mat = layer * 2 + blockIdx.z;
    const unsigned* WT = g_wt + (size_t)mat * (DIM * DIM / 2);

    int tid = threadIdx.x;
    int wid = tid >> 5, lane = tid & 31;
    int warp_m = wid & 1;
    int warp_n = wid >> 1;
    int g4 = lane >> 2;
    int t4 = lane & 3;

    int xrow[4], xk4[4];
    int hrow[2], hc[2];
#pragma unroll
    for (int t = 0; t < 4; t++) {
        int f = tid + t * 256;
        xrow[t] = f >> 3;  xk4[t] = (f & 7) << 2;
    }
#pragma unroll
    for (int t = 0; t < 2; t++) {
        int f = tid + t * 256;
        hrow[t] = f >> 2;  hc[t] = (f & 3) << 2;
    }

    float4 xv[4];
    uint4  hv[2];
    uint4  wv[2];

    auto load_tile = [&](int k0) {
        int kw = k0 >> 1;
        if (layer == 0) {
#pragma unroll
            for (int t = 0; t < 4; t++) {
                int gr = m0 + xrow[t];
                xv[t] = make_float4(0.f, 0.f, 0.f, 0.f);
                if (gr < N_NODES)
                    xv[t] = *(const float4*)(Xin + (size_t)gr * DIM + k0 + xk4[t]);
            }
        } else {
#pragma unroll
            for (int t = 0; t < 2; t++) {
                int gr = m0 + hrow[t];
                hv[t] = make_uint4(0u, 0u, 0u, 0u);
                if (gr < N_NODES)
                    hv[t] = *(const uint4*)(g_hh + (size_t)gr * (DIM / 2) + kw + hc[t]);
            }
        }
#pragma unroll
        for (int t = 0; t < 2; t++)
            wv[t] = *(const uint4*)(WT + (size_t)(n0 + hrow[t]) * (DIM / 2) + kw + hc[t]);
    };

    auto store_tile = [&](int p) {
        unsigned* As = As2[p];
        unsigned* Bs = Bs2[p];
        if (layer == 0) {
#pragma unroll
            for (int t = 0; t < 4; t++) {
                uint2 u;
                u.x = h2u(xv[t].x, xv[t].y);
                u.y = h2u(xv[t].z, xv[t].w);
                *(uint2*)&As[xrow[t] * ST + (xk4[t] >> 1)] = u;
            }
        } else {
#pragma unroll
            for (int t = 0; t < 2; t++)
                *(uint4*)&As[hrow[t] * ST + hc[t]] = hv[t];
        }
#pragma unroll
        for (int t = 0; t < 2; t++)
            *(uint4*)&Bs[hrow[t] * ST + hc[t]] = wv[t];
    };

    float acc[4][4][4];
#pragma unroll
    for (int mt = 0; mt < 4; mt++)
#pragma unroll
        for (int nt = 0; nt < 4; nt++)
#pragma unroll
            for (int r = 0; r < 4; r++) acc[mt][nt][r] = 0.f;

    load_tile(0);
    store_tile(0);
    __syncthreads();
    load_tile(TBK);

    uint32_t a_lane_off = (uint32_t)(((warp_m * 64 + (lane & 15)) * ST + (lane >> 4) * 4) * 4);
    uint32_t b_lane_off = (uint32_t)(((warp_n * 32 + (lane & 7)) * ST + ((lane >> 3) & 1) * 4) * 4);

    int p = 0;
    for (int k0 = 0; k0 < DIM; k0 += TBK) {
        uint32_t sa  = (uint32_t)__cvta_generic_to_shared(As2[p]) + a_lane_off;
        uint32_t sbb = (uint32_t)__cvta_generic_to_shared(Bs2[p]) + b_lane_off;

#pragma unroll
        for (int ks = 0; ks < 2; ks++) {
            unsigned b[4][2];
#pragma unroll
            for (int nt = 0; nt < 4; nt++)
                ldsm_x2(b[nt][0], b[nt][1], sbb + (uint32_t)((nt * 8 * ST + ks * 8) * 4));
#pragma unroll
            for (int mt = 0; mt < 4; mt++) {
                unsigned a0, a1, a2, a3;
                ldsm_x4(a0, a1, a2, a3, sa + (uint32_t)((mt * 16 * ST + ks * 8) * 4));
#pragma unroll
                for (int nt = 0; nt < 4; nt++)
                    mma_f16(acc[mt][nt], a0, a1, a2, a3, b[nt][0], b[nt][1]);
            }
        }

        if (k0 + TBK < DIM) {
            store_tile(1 - p);
            if (k0 + 2 * TBK < DIM) load_tile(k0 + 2 * TBK);
            __syncthreads();
        }
        p ^= 1;
    }

    unsigned* Cout = (blockIdx.z == 0) ? g_xlh : g_xrh;
#pragma unroll
    for (int mt = 0; mt < 4; mt++) {
        int r0 = m0 + warp_m * 64 + mt * 16 + g4;
#pragma unroll
        for (int nt = 0; nt < 4; nt++) {
            int c = n0 + warp_n * 32 + nt * 8 + t4 * 2;
            if (r0 < N_NODES)
                Cout[((size_t)r0 * DIM + c) >> 1] =
                    h2u(acc[mt][nt][0], acc[mt][nt][1]);
            if (r0 + 8 < N_NODES)
                Cout[((size_t)(r0 + 8) * DIM + c) >> 1] =
                    h2u(acc[mt][nt][2], acc[mt][nt][3]);
        }
    }
}

// ---------------- fused GATv2 node kernel: 2 warps per node ----------------
// Warp (node, half) handles heads 4*half..4*half+3 = channels 128*half..+127.
// Per edge: one uint2 gather (4 channels/lane), one dot+3-shuffle chain,
// 4-channel accumulate. Edge order per head identical to the 1-warp version.
__device__ __forceinline__ float dot4_lrelu(float4 a, float4 l, float4 r) {
    float z, s;
    z = l.x + r.x; z = z > 0.f ? z : 0.2f * z; s  = a.x * z;
    z = l.y + r.y; z = z > 0.f ? z : 0.2f * z; s += a.y * z;
    z = l.z + r.z; z = z > 0.f ? z : 0.2f * z; s += a.z * z;
    z = l.w + r.w; z = z > 0.f ? z : 0.2f * z; s += a.w * z;
    return s;
}

__device__ __forceinline__ float4 u2f4(uint2 u) {
    float2 lo = __half22float2(*(__half2*)&u.x);
    float2 hi = __half22float2(*(__half2*)&u.y);
    return make_float4(lo.x, lo.y, hi.x, hi.y);
}

#define WPB 8   // warps per block

__global__ __launch_bounds__(WPB * 32)
void gat_node_kernel(const float* __restrict__ att,
                     const float* __restrict__ bias,
                     float* __restrict__ outp, int mode) {
    int gw = blockIdx.x * WPB + (threadIdx.x >> 5);
    if (gw >= 2 * N_NODES) return;
    int node = gw >> 1;
    int half = gw & 1;
    int lane = threadIdx.x & 31;
    int grp  = lane >> 3;
    int sub  = lane & 7;
    int ci   = half * 32 + lane;   // float4/uint2 channel-group index (0..63)

    float4 a = ((const float4*)att)[ci];
    float4 r = u2f4(((const uint2*)(g_xrh + (size_t)node * (DIM / 2)))[ci]);

    int beg = g_roff[node], end = g_roff[node + 1];

    float4 acc = make_float4(0.f, 0.f, 0.f, 0.f);
    float  s   = 0.f;

    auto proc = [&](uint2 u) {
        float4 l = u2f4(u);
        float sl = dot4_lrelu(a, l, r);
#pragma unroll
        for (int off = 4; off; off >>= 1)
            sl += __shfl_xor_sync(0xffffffffu, sl, off);
        float ex = 0.f;
        if (sub == 0) ex = __expf(sl);
        float exl = __shfl_sync(0xffffffffu, ex, grp * 8);
        acc.x += exl * l.x; acc.y += exl * l.y;
        acc.z += exl * l.z; acc.w += exl * l.w;
        s += exl;
    };

    // depth-2 prefetch over the CSR edge list
    uint2 c0, c1;
    c1 = make_uint2(0u, 0u);
    c0 = ((const uint2*)(g_xlh + (size_t)g_csr[beg] * (DIM / 2)))[ci];
    if (beg + 1 < end)
        c1 = ((const uint2*)(g_xlh + (size_t)g_csr[beg + 1] * (DIM / 2)))[ci];

    for (int e = beg; e < end; e += 2) {
        uint2 n0 = make_uint2(0u, 0u), n1 = n0;
        if (e + 2 < end)
            n0 = ((const uint2*)(g_xlh + (size_t)g_csr[e + 2] * (DIM / 2)))[ci];
        if (e + 3 < end)
            n1 = ((const uint2*)(g_xlh + (size_t)g_csr[e + 3] * (DIM / 2)))[ci];

        proc(c0);
        if (e + 1 < end) proc(c1);

        c0 = n0; c1 = n1;
    }

    float inv = 1.f / s;
    float4 b = ((const float4*)bias)[ci];
    float4 v = make_float4(acc.x * inv + b.x, acc.y * inv + b.y,
                           acc.z * inv + b.z, acc.w * inv + b.w);

    if (mode == 0) {   // ELU -> half2-packed layer-2 input
        v.x = v.x > 0.f ? v.x : expm1f(v.x);
        v.y = v.y > 0.f ? v.y : expm1f(v.y);
        v.z = v.z > 0.f ? v.z : expm1f(v.z);
        v.w = v.w > 0.f ? v.w : expm1f(v.w);
        ((uint2*)(g_hh + (size_t)node * (DIM / 2)))[ci] =
            make_uint2(h2u(v.x, v.y), h2u(v.z, v.w));
    } else {
        ((float4*)(outp + (size_t)node * DIM))[ci] = v;
    }
}

// ---------------- host entry ----------------
extern "C" void kernel_launch(void* const* d_in, const int* in_sizes, int n_in,
                              void* d_out, int out_size) {
    const float* x    = (const float*)d_in[0];
    const void*  eidx = d_in[1];
    const float* Wl1  = (const float*)d_in[2];
    const float* Wr1  = (const float*)d_in[3];
    const float* att1 = (const float*)d_in[4];
    const float* b1   = (const float*)d_in[5];
    const float* Wl2  = (const float*)d_in[6];
    const float* Wr2  = (const float*)d_in[7];
    const float* att2 = (const float*)d_in[8];
    const float* b2   = (const float*)d_in[9];
    float*       outp = (float*)d_out;

    dim3 ggemm((N_NODES + TBM - 1) / TBM, DIM / TBN, 2);
    dim3 gnode((2 * N_NODES + WPB - 1) / WPB);

    // ---- one-time prep: W transpose + CSR build ----
    detect_kernel  <<<1, 1>>>((const int*)eidx);
    convwt_kernel  <<<dim3(128, 4), 256>>>(Wl1, Wr1, Wl2, Wr2);
    hist_kernel    <<<(N_EDGES + 255) / 256, 256>>>(eidx);
    scan1_kernel   <<<NBLK, 256>>>();
    scan3_kernel   <<<NBLK, 256>>>();
    scatter_kernel <<<(N_EDGES + 255) / 256, 256>>>(eidx);

    // ---- layer 1 ----
    gemm_f16_kernel<<<ggemm, 256>>>(x, 0);
    gat_node_kernel<<<gnode, WPB * 32>>>(att1, b1, outp, 0);

    // ---- layer 2 ----
    gemm_f16_kernel<<<ggemm, 256>>>(x, 1);
    gat_node_kernel<<<gnode, WPB * 32>>>(att2, b2, outp, 1);
}